// round 1
// baseline (speedup 1.0000x reference)
#include <cuda_runtime.h>
#include <cuda_bf16.h>
#include <math.h>

// ---------------- problem constants ----------------
#define NN 50000
#define EE 400000
#define HH 8
#define CC 128
#define EMB 256
#define NG 64
#define QKVS_W 3328   // 1024 q + 1024 k + 1024 v + 128 skip
#define OFF_K 1024
#define OFF_V 2048
#define OFF_S 3072

// ---------------- scratch (device globals; no allocation allowed) ----------------
__device__ float g_h[(size_t)NN * EMB];          // embedded features (layer0 input)
__device__ float g_qkvs[(size_t)NN * QKVS_W];    // fused projection output
__device__ float g_attn[(size_t)NN * CC];        // head-mean attention output
__device__ float g_h1[(size_t)NN * CC];          // layer0 output (residual for layer1)
__device__ float g_h2[(size_t)NN * CC];          // layer1 output
__device__ float g_Wcat[(size_t)EMB * QKVS_W];   // packed weights (max K=256)
__device__ float g_bcat[QKVS_W];
__device__ float g_pool[NG * CC];
__device__ float g_cnt[NG];
__device__ int   g_deg[NN];
__device__ int   g_rowptr[NN + 1];
__device__ int   g_wofs[NN];
__device__ int   g_col[EE];

// ---------------- CSR build ----------------
__global__ void hist_kernel(const int* __restrict__ dst, int* __restrict__ deg, int E) {
    int e = blockIdx.x * blockDim.x + threadIdx.x;
    if (e < E) atomicAdd(&deg[dst[e]], 1);
}

__global__ void scan_kernel(const int* __restrict__ deg, int* __restrict__ rowptr, int n) {
    // single block, 1024 threads; sequential chunked Hillis-Steele scan
    __shared__ int temp[1024];
    __shared__ int carry;
    int tid = threadIdx.x;
    if (tid == 0) { carry = 0; rowptr[0] = 0; }
    __syncthreads();
    for (int base = 0; base < n; base += 1024) {
        int i = base + tid;
        int v = (i < n) ? deg[i] : 0;
        temp[tid] = v;
        __syncthreads();
        #pragma unroll
        for (int off = 1; off < 1024; off <<= 1) {
            int t = (tid >= off) ? temp[tid - off] : 0;
            __syncthreads();
            temp[tid] += t;
            __syncthreads();
        }
        if (i < n) rowptr[i + 1] = carry + temp[tid];
        __syncthreads();
        if (tid == 0) carry += temp[1023];
        __syncthreads();
    }
}

__global__ void copyofs_kernel(const int* __restrict__ rowptr, int* __restrict__ wofs, int n) {
    int i = blockIdx.x * blockDim.x + threadIdx.x;
    if (i < n) wofs[i] = rowptr[i];
}

__global__ void scatter_kernel(const int* __restrict__ src, const int* __restrict__ dst,
                               int* __restrict__ wofs, int* __restrict__ col, int E) {
    int e = blockIdx.x * blockDim.x + threadIdx.x;
    if (e < E) {
        int p = atomicAdd(&wofs[dst[e]], 1);
        col[p] = src[e];
    }
}

// ---------------- embedding gather ----------------
__global__ void embed_kernel(const int* __restrict__ x, const float* __restrict__ emb,
                             float* __restrict__ h, int N) {
    int idx = blockIdx.x * blockDim.x + threadIdx.x;
    if (idx >= N * (EMB / 4)) return;
    int n  = idx >> 6;                 // EMB/4 = 64 float4 per row
    int c4 = (idx & 63) << 2;
    *(float4*)(h + (size_t)n * EMB + c4) =
        *(const float4*)(emb + (size_t)x[n] * EMB + c4);
}

// ---------------- weight packing [K, 3328] ----------------
__global__ void pack_kernel(const float* __restrict__ Wq, const float* __restrict__ Wk,
                            const float* __restrict__ Wv, const float* __restrict__ Ws,
                            const float* __restrict__ bq, const float* __restrict__ bk,
                            const float* __restrict__ bv, const float* __restrict__ bs,
                            float* __restrict__ Wcat, float* __restrict__ bcat, int K) {
    int idx = blockIdx.x * blockDim.x + threadIdx.x;
    if (idx >= K * QKVS_W) return;
    int k = idx / QKVS_W, o = idx - k * QKVS_W;
    float v;
    if (o < 1024)      v = Wq[k * 1024 + o];
    else if (o < 2048) v = Wk[k * 1024 + (o - 1024)];
    else if (o < 3072) v = Wv[k * 1024 + (o - 2048)];
    else               v = Ws[k * 128  + (o - 3072)];
    Wcat[idx] = v;
    if (k == 0) {
        float b;
        if (o < 1024)      b = bq[o];
        else if (o < 2048) b = bk[o - 1024];
        else if (o < 3072) b = bv[o - 2048];
        else               b = bs[o - 3072];
        bcat[o] = b;
    }
}

// ---------------- SGEMM 128x128x16, 8x8 regs, bias epilogue ----------------
__global__ __launch_bounds__(256)
void sgemm_bias_kernel(const float* __restrict__ A, const float* __restrict__ B,
                       const float* __restrict__ bias, float* __restrict__ C,
                       int M, int N, int K) {
    __shared__ float As[16][128];
    __shared__ float Bs[16][128];
    int bn = blockIdx.x * 128;
    int bm = blockIdx.y * 128;
    int tid = threadIdx.x;
    int tx = tid & 15, ty = tid >> 4;

    float acc[8][8];
    #pragma unroll
    for (int i = 0; i < 8; i++)
        #pragma unroll
        for (int j = 0; j < 8; j++) acc[i][j] = 0.f;

    for (int k0 = 0; k0 < K; k0 += 16) {
        #pragma unroll
        for (int i = 0; i < 2; i++) {
            int t = tid + i * 256;
            int r = t >> 2, kc = (t & 3) << 2;
            float4 av = make_float4(0.f, 0.f, 0.f, 0.f);
            if (bm + r < M)
                av = *(const float4*)(A + (size_t)(bm + r) * K + k0 + kc);
            As[kc + 0][r] = av.x; As[kc + 1][r] = av.y;
            As[kc + 2][r] = av.z; As[kc + 3][r] = av.w;
        }
        #pragma unroll
        for (int i = 0; i < 2; i++) {
            int t = tid + i * 256;
            int r = t >> 5, c4 = (t & 31) << 2;
            *(float4*)&Bs[r][c4] = *(const float4*)(B + (size_t)(k0 + r) * N + bn + c4);
        }
        __syncthreads();
        #pragma unroll
        for (int kk = 0; kk < 16; kk++) {
            float a[8], b[8];
            #pragma unroll
            for (int i = 0; i < 8; i++) a[i] = As[kk][ty * 8 + i];
            #pragma unroll
            for (int j = 0; j < 8; j++) b[j] = Bs[kk][tx * 8 + j];
            #pragma unroll
            for (int i = 0; i < 8; i++)
                #pragma unroll
                for (int j = 0; j < 8; j++) acc[i][j] += a[i] * b[j];
        }
        __syncthreads();
    }
    #pragma unroll
    for (int i = 0; i < 8; i++) {
        int r = bm + ty * 8 + i;
        if (r >= M) break;
        #pragma unroll
        for (int j = 0; j < 8; j += 4) {
            int cidx = bn + tx * 8 + j;
            float4 o;
            o.x = acc[i][j + 0] + bias[cidx + 0];
            o.y = acc[i][j + 1] + bias[cidx + 1];
            o.z = acc[i][j + 2] + bias[cidx + 2];
            o.w = acc[i][j + 3] + bias[cidx + 3];
            *(float4*)(C + (size_t)r * N + cidx) = o;
        }
    }
}

// ---------------- edge attention: 1 block = 1 dst node, 1 warp = 1 head ----------------
__global__ __launch_bounds__(256)
void attn_kernel(const float* __restrict__ qkvs, const int* __restrict__ rowptr,
                 const int* __restrict__ col, float* __restrict__ attn) {
    int node = blockIdx.x;
    int wid  = threadIdx.x >> 5;   // head
    int lane = threadIdx.x & 31;
    const float scale = 0.0883883476483184f; // 1/sqrt(128)

    float4 q = *(const float4*)(qkvs + (size_t)node * QKVS_W + wid * CC + lane * 4);
    int e0 = rowptr[node], e1 = rowptr[node + 1];

    float m = -1e30f, den = 0.f;
    float4 acc = make_float4(0.f, 0.f, 0.f, 0.f);
    for (int e = e0; e < e1; e++) {
        int s = col[e];
        const float* base = qkvs + (size_t)s * QKVS_W + wid * CC + lane * 4;
        float4 kv = *(const float4*)(base + OFF_K);
        float d = q.x * kv.x + q.y * kv.y + q.z * kv.z + q.w * kv.w;
        #pragma unroll
        for (int off = 16; off; off >>= 1) d += __shfl_xor_sync(0xffffffffu, d, off);
        float logit = d * scale;
        float mn   = fmaxf(m, logit);
        float corr = __expf(m - mn);
        float p    = __expf(logit - mn);
        float4 vv = *(const float4*)(base + OFF_V);
        den   = den * corr + p;
        acc.x = acc.x * corr + p * vv.x;
        acc.y = acc.y * corr + p * vv.y;
        acc.z = acc.z * corr + p * vv.z;
        acc.w = acc.w * corr + p * vv.w;
        m = mn;
    }
    float inv = 1.f / (den + 1e-16f);
    __shared__ float sm[HH * CC];
    sm[wid * CC + lane * 4 + 0] = acc.x * inv;
    sm[wid * CC + lane * 4 + 1] = acc.y * inv;
    sm[wid * CC + lane * 4 + 2] = acc.z * inv;
    sm[wid * CC + lane * 4 + 3] = acc.w * inv;
    __syncthreads();
    if (threadIdx.x < CC) {
        float s = 0.f;
        #pragma unroll
        for (int h = 0; h < HH; h++) s += sm[h * CC + threadIdx.x];
        attn[(size_t)node * CC + threadIdx.x] = s * 0.125f;
    }
}

// ---------------- beta-gate + (residual) + LayerNorm + ReLU: 1 warp = 1 node ----------------
__global__ __launch_bounds__(256)
void gate_ln_kernel(const float* __restrict__ attn, const float* __restrict__ qkvs,
                    const float* __restrict__ Wb, const float* __restrict__ gam,
                    const float* __restrict__ bet, const float* __restrict__ res,
                    float* __restrict__ out, int N) {
    int node = blockIdx.x * 8 + (threadIdx.x >> 5);
    if (node >= N) return;
    int lane = threadIdx.x & 31;
    int c = lane * 4;

    float4 a  = *(const float4*)(attn + (size_t)node * CC + c);
    float4 xr = *(const float4*)(qkvs + (size_t)node * QKVS_W + OFF_S + c);
    float4 w0 = *(const float4*)(Wb + c);
    float4 w1 = *(const float4*)(Wb + 128 + c);
    float4 w2 = *(const float4*)(Wb + 256 + c);

    float t = a.x * w0.x + a.y * w0.y + a.z * w0.z + a.w * w0.w
            + xr.x * w1.x + xr.y * w1.y + xr.z * w1.z + xr.w * w1.w
            + (a.x - xr.x) * w2.x + (a.y - xr.y) * w2.y
            + (a.z - xr.z) * w2.z + (a.w - xr.w) * w2.w;
    #pragma unroll
    for (int off = 16; off; off >>= 1) t += __shfl_xor_sync(0xffffffffu, t, off);
    float beta = 1.f / (1.f + __expf(-t));

    float4 y;
    y.x = beta * xr.x + (1.f - beta) * a.x;
    y.y = beta * xr.y + (1.f - beta) * a.y;
    y.z = beta * xr.z + (1.f - beta) * a.z;
    y.w = beta * xr.w + (1.f - beta) * a.w;
    if (res) {
        float4 r = *(const float4*)(res + (size_t)node * CC + c);
        y.x += r.x; y.y += r.y; y.z += r.z; y.w += r.w;
    }
    // LayerNorm over 128 (two-pass in registers)
    float s = y.x + y.y + y.z + y.w;
    #pragma unroll
    for (int off = 16; off; off >>= 1) s += __shfl_xor_sync(0xffffffffu, s, off);
    float mu = s * (1.f / 128.f);
    float dx0 = y.x - mu, dx1 = y.y - mu, dx2 = y.z - mu, dx3 = y.w - mu;
    float q = dx0 * dx0 + dx1 * dx1 + dx2 * dx2 + dx3 * dx3;
    #pragma unroll
    for (int off = 16; off; off >>= 1) q += __shfl_xor_sync(0xffffffffu, q, off);
    float rstd = rsqrtf(q * (1.f / 128.f) + 1e-5f);
    float4 gg = *(const float4*)(gam + c);
    float4 bb = *(const float4*)(bet + c);
    float4 o;
    o.x = fmaxf(dx0 * rstd * gg.x + bb.x, 0.f);
    o.y = fmaxf(dx1 * rstd * gg.y + bb.y, 0.f);
    o.z = fmaxf(dx2 * rstd * gg.z + bb.z, 0.f);
    o.w = fmaxf(dx3 * rstd * gg.w + bb.w, 0.f);
    *(float4*)(out + (size_t)node * CC + c) = o;
}

// ---------------- pooling ----------------
__global__ void pool_kernel(const float* __restrict__ h, const int* __restrict__ batch,
                            float* __restrict__ psum, int N) {
    int idx = blockIdx.x * blockDim.x + threadIdx.x;
    if (idx >= N * CC) return;
    int n = idx >> 7, c = idx & 127;
    atomicAdd(&psum[batch[n] * CC + c], h[idx]);
}

__global__ void cnt_kernel(const int* __restrict__ batch, float* __restrict__ cnt, int N) {
    int n = blockIdx.x * blockDim.x + threadIdx.x;
    if (n < N) atomicAdd(&cnt[batch[n]], 1.0f);
}

// ---------------- classifier: 64 threads, 1 per graph ----------------
__global__ void cls_kernel(const float* __restrict__ psum, const float* __restrict__ cnt,
                           const float* __restrict__ Wc1, const float* __restrict__ bc1,
                           const float* __restrict__ Wc2, const float* __restrict__ bc2,
                           float* __restrict__ out) {
    int g = threadIdx.x;
    if (g >= NG) return;
    float invc = 1.f / fmaxf(cnt[g], 1.f);
    float pooled[CC];
    #pragma unroll 8
    for (int c = 0; c < CC; c++) pooled[c] = psum[g * CC + c] * invc;
    float r = bc2[0];
    for (int j = 0; j < 64; j++) {
        float z = bc1[j];
        #pragma unroll 8
        for (int c = 0; c < CC; c++) z += pooled[c] * Wc1[c * 64 + j];
        r += fmaxf(z, 0.f) * Wc2[j];
    }
    out[g] = r;
}

// ---------------- launch ----------------
extern "C" void kernel_launch(void* const* d_in, const int* in_sizes, int n_in,
                              void* d_out, int out_size) {
    const int N = NN, E = EE;
    const int*   x     = (const int*)d_in[0];
    const int*   ei    = (const int*)d_in[1];
    const int*   src   = ei;
    const int*   dst   = ei + E;
    const int*   batch = (const int*)d_in[2];
    const float* emb   = (const float*)d_in[3];

    const float *Wq0 = (const float*)d_in[4],  *bq0 = (const float*)d_in[5];
    const float *Wk0 = (const float*)d_in[6],  *bk0 = (const float*)d_in[7];
    const float *Wv0 = (const float*)d_in[8],  *bv0 = (const float*)d_in[9];
    const float *Ws0 = (const float*)d_in[10], *bs0 = (const float*)d_in[11];
    const float *Wb0 = (const float*)d_in[12];
    const float *g0  = (const float*)d_in[13], *be0 = (const float*)d_in[14];
    const float *Wq1 = (const float*)d_in[15], *bq1 = (const float*)d_in[16];
    const float *Wk1 = (const float*)d_in[17], *bk1 = (const float*)d_in[18];
    const float *Wv1 = (const float*)d_in[19], *bv1 = (const float*)d_in[20];
    const float *Ws1 = (const float*)d_in[21], *bs1 = (const float*)d_in[22];
    const float *Wb1 = (const float*)d_in[23];
    const float *g1  = (const float*)d_in[24], *be1 = (const float*)d_in[25];
    const float *Wc1 = (const float*)d_in[26], *bc1 = (const float*)d_in[27];
    const float *Wc2 = (const float*)d_in[28], *bc2 = (const float*)d_in[29];

    float *h, *qkvs, *attn, *h1, *h2, *Wcat, *bcat, *pool, *cnt;
    int *deg, *rowptr, *wofs, *col;
    cudaGetSymbolAddress((void**)&h,      g_h);
    cudaGetSymbolAddress((void**)&qkvs,   g_qkvs);
    cudaGetSymbolAddress((void**)&attn,   g_attn);
    cudaGetSymbolAddress((void**)&h1,     g_h1);
    cudaGetSymbolAddress((void**)&h2,     g_h2);
    cudaGetSymbolAddress((void**)&Wcat,   g_Wcat);
    cudaGetSymbolAddress((void**)&bcat,   g_bcat);
    cudaGetSymbolAddress((void**)&pool,   g_pool);
    cudaGetSymbolAddress((void**)&cnt,    g_cnt);
    cudaGetSymbolAddress((void**)&deg,    g_deg);
    cudaGetSymbolAddress((void**)&rowptr, g_rowptr);
    cudaGetSymbolAddress((void**)&wofs,   g_wofs);
    cudaGetSymbolAddress((void**)&col,    g_col);

    // CSR build (by dst)
    cudaMemsetAsync(deg, 0, N * sizeof(int));
    hist_kernel<<<(E + 255) / 256, 256>>>(dst, deg, E);
    scan_kernel<<<1, 1024>>>(deg, rowptr, N);
    copyofs_kernel<<<(N + 255) / 256, 256>>>(rowptr, wofs, N);
    scatter_kernel<<<(E + 255) / 256, 256>>>(src, dst, wofs, col, E);

    // embedding
    embed_kernel<<<(N * (EMB / 4) + 255) / 256, 256>>>(x, emb, h, N);

    dim3 ggrid(QKVS_W / 128, (N + 127) / 128);

    // ---- layer 0 (K = 256) ----
    pack_kernel<<<(256 * QKVS_W + 255) / 256, 256>>>(Wq0, Wk0, Wv0, Ws0, bq0, bk0, bv0, bs0,
                                                     Wcat, bcat, 256);
    sgemm_bias_kernel<<<ggrid, 256>>>(h, Wcat, bcat, qkvs, N, QKVS_W, 256);
    attn_kernel<<<N, 256>>>(qkvs, rowptr, col, attn);
    gate_ln_kernel<<<(N + 7) / 8, 256>>>(attn, qkvs, Wb0, g0, be0, (const float*)nullptr, h1, N);

    // ---- layer 1 (K = 128, residual) ----
    pack_kernel<<<(128 * QKVS_W + 255) / 256, 256>>>(Wq1, Wk1, Wv1, Ws1, bq1, bk1, bv1, bs1,
                                                     Wcat, bcat, 128);
    sgemm_bias_kernel<<<ggrid, 256>>>(h1, Wcat, bcat, qkvs, N, QKVS_W, 128);
    attn_kernel<<<N, 256>>>(qkvs, rowptr, col, attn);
    gate_ln_kernel<<<(N + 7) / 8, 256>>>(attn, qkvs, Wb1, g1, be1, h1, h2, N);

    // ---- pool + classifier ----
    cudaMemsetAsync(pool, 0, NG * CC * sizeof(float));
    cudaMemsetAsync(cnt, 0, NG * sizeof(float));
    pool_kernel<<<(N * CC + 255) / 256, 256>>>(h2, batch, pool, N);
    cnt_kernel<<<(N + 255) / 256, 256>>>(batch, cnt, N);
    cls_kernel<<<1, 64>>>(pool, cnt, Wc1, bc1, Wc2, bc2, (float*)d_out);
}

// round 2
// speedup vs baseline: 1.7854x; 1.7854x over previous
#include <cuda_runtime.h>
#include <cuda_bf16.h>
#include <math.h>
#include <stdint.h>

// ---------------- problem constants ----------------
#define NN 50000
#define EE 400000
#define HH 8
#define CC 128
#define EMB 256
#define NG 64
#define QKVS_W 3328   // 1024 q + 1024 k + 1024 v + 128 skip
#define OFF_K 1024
#define OFF_V 2048
#define OFF_S 3072

// ---------------- scratch (device globals; no allocation allowed) ----------------
__device__ float g_h[(size_t)NN * EMB];          // embedded features (layer0 input)
__device__ float g_qkvs[(size_t)NN * QKVS_W];    // fused projection output
__device__ float g_attn[(size_t)NN * CC];        // head-mean attention output
__device__ float g_h1[(size_t)NN * CC];          // layer0 output (residual for layer1)
__device__ float g_h2[(size_t)NN * CC];          // layer1 output
__device__ float g_Wcat[(size_t)EMB * QKVS_W];   // packed weights (max K=256)
__device__ float g_bcat[QKVS_W];
__device__ float g_pool[NG * CC];
__device__ float g_cnt[NG];
__device__ int   g_deg[NN];
__device__ int   g_rowptr[NN + 1];
__device__ int   g_wofs[NN];
__device__ int   g_col[EE];
__device__ int   g_bsum[256];
__device__ int   g_bsum2[256];

// ---------------- CSR build ----------------
__global__ void hist_kernel(const int* __restrict__ dst, int* __restrict__ deg, int E) {
    int e = blockIdx.x * blockDim.x + threadIdx.x;
    if (e < E) atomicAdd(&deg[dst[e]], 1);
}

// block-local inclusive scan of deg into rowptr[i+1], block totals to bsum
__global__ void scan_block_kernel(const int* __restrict__ deg, int* __restrict__ rowptr,
                                  int* __restrict__ bsum, int n) {
    __shared__ int s[256];
    int i = blockIdx.x * 256 + threadIdx.x;
    int v = (i < n) ? deg[i] : 0;
    s[threadIdx.x] = v;
    __syncthreads();
    #pragma unroll
    for (int off = 1; off < 256; off <<= 1) {
        int t = (threadIdx.x >= off) ? s[threadIdx.x - off] : 0;
        __syncthreads();
        s[threadIdx.x] += t;
        __syncthreads();
    }
    if (i < n) rowptr[i + 1] = s[threadIdx.x];
    if (threadIdx.x == 255) bsum[blockIdx.x] = s[255];
}

__global__ void scan_bsum_kernel(const int* __restrict__ bsum, int* __restrict__ bsum2, int nb) {
    __shared__ int s[256];
    int t = threadIdx.x;
    int v = (t < nb) ? bsum[t] : 0;
    s[t] = v;
    __syncthreads();
    #pragma unroll
    for (int off = 1; off < 256; off <<= 1) {
        int x = (t >= off) ? s[t - off] : 0;
        __syncthreads();
        s[t] += x;
        __syncthreads();
    }
    if (t < nb) bsum2[t] = s[t] - v;   // exclusive
}

__global__ void scan_add_kernel(int* __restrict__ rowptr, const int* __restrict__ bsum2, int n) {
    int i = blockIdx.x * 256 + threadIdx.x;
    if (i < n) rowptr[i + 1] += bsum2[blockIdx.x];
    if (i == 0) rowptr[0] = 0;
}

__global__ void copyofs_kernel(const int* __restrict__ rowptr, int* __restrict__ wofs, int n) {
    int i = blockIdx.x * blockDim.x + threadIdx.x;
    if (i < n) wofs[i] = rowptr[i];
}

__global__ void scatter_kernel(const int* __restrict__ src, const int* __restrict__ dst,
                               int* __restrict__ wofs, int* __restrict__ col, int E) {
    int e = blockIdx.x * blockDim.x + threadIdx.x;
    if (e < E) {
        int p = atomicAdd(&wofs[dst[e]], 1);
        col[p] = src[e];
    }
}

// ---------------- embedding gather ----------------
__global__ void embed_kernel(const int* __restrict__ x, const float* __restrict__ emb,
                             float* __restrict__ h, int N) {
    int idx = blockIdx.x * blockDim.x + threadIdx.x;
    if (idx >= N * (EMB / 4)) return;
    int n  = idx >> 6;
    int c4 = (idx & 63) << 2;
    *(float4*)(h + (size_t)n * EMB + c4) =
        *(const float4*)(emb + (size_t)x[n] * EMB + c4);
}

// ---------------- weight packing [K, 3328] ----------------
__global__ void pack_kernel(const float* __restrict__ Wq, const float* __restrict__ Wk,
                            const float* __restrict__ Wv, const float* __restrict__ Ws,
                            const float* __restrict__ bq, const float* __restrict__ bk,
                            const float* __restrict__ bv, const float* __restrict__ bs,
                            float* __restrict__ Wcat, float* __restrict__ bcat, int K) {
    int idx = blockIdx.x * blockDim.x + threadIdx.x;
    if (idx >= K * QKVS_W) return;
    int k = idx / QKVS_W, o = idx - k * QKVS_W;
    float v;
    if (o < 1024)      v = Wq[k * 1024 + o];
    else if (o < 2048) v = Wk[k * 1024 + (o - 1024)];
    else if (o < 3072) v = Wv[k * 1024 + (o - 2048)];
    else               v = Ws[k * 128  + (o - 3072)];
    Wcat[idx] = v;
    if (k == 0) {
        float b;
        if (o < 1024)      b = bq[o];
        else if (o < 2048) b = bk[o - 1024];
        else if (o < 3072) b = bv[o - 2048];
        else               b = bs[o - 3072];
        bcat[o] = b;
    }
}

// ---------------- TF32 tensor-core GEMM: 128x256x16 block, 8 warps of 64x64 ----------------
__device__ __forceinline__ uint32_t f2tf(float f) {
    uint32_t u;
    asm("cvt.rna.tf32.f32 %0, %1;" : "=r"(u) : "f"(f));
    return u;
}

__device__ __forceinline__ void mma_tf32(float* c, const uint32_t* a, const uint32_t* b) {
    asm volatile(
        "mma.sync.aligned.m16n8k8.row.col.f32.tf32.tf32.f32 "
        "{%0,%1,%2,%3}, {%4,%5,%6,%7}, {%8,%9}, {%0,%1,%2,%3};"
        : "+f"(c[0]), "+f"(c[1]), "+f"(c[2]), "+f"(c[3])
        : "r"(a[0]), "r"(a[1]), "r"(a[2]), "r"(a[3]), "r"(b[0]), "r"(b[1]));
}

#define GBM 128
#define GBN 256
#define GBK 16
#define AS_STRIDE 20    // 16 + 4 pad: conflict-free for fragment LDS pattern
#define BS_STRIDE 264   // 256 + 8 pad: stride % 32 == 8 -> conflict-free

__global__ __launch_bounds__(256, 1)
void gemm_tf32_kernel(const float* __restrict__ A, const float* __restrict__ B,
                      const float* __restrict__ bias, float* __restrict__ C,
                      int M, int N, int K) {
    __shared__ float As[GBM * AS_STRIDE];
    __shared__ float Bs[GBK * BS_STRIDE];

    int bm = blockIdx.y * GBM;
    int bn = blockIdx.x * GBN;
    int tid = threadIdx.x;
    int wid = tid >> 5, lane = tid & 31;
    int wm = (wid >> 2) * 64;      // warp row base within block
    int wn = (wid & 3) * 64;       // warp col base within block
    int gid = lane >> 2, tig = lane & 3;

    float acc[4][8][4];
    #pragma unroll
    for (int i = 0; i < 4; i++)
        #pragma unroll
        for (int j = 0; j < 8; j++)
            #pragma unroll
            for (int q = 0; q < 4; q++) acc[i][j][q] = 0.f;

    float4 ra[2], rb[4];

    // ---- load tile 0 to regs ----
    #pragma unroll
    for (int i = 0; i < 2; i++) {
        int f = tid + i * 256;
        int r = f >> 2, kc = (f & 3) << 2;
        ra[i] = (bm + r < M) ? *(const float4*)(A + (size_t)(bm + r) * K + kc)
                             : make_float4(0.f, 0.f, 0.f, 0.f);
    }
    #pragma unroll
    for (int i = 0; i < 4; i++) {
        int f = tid + i * 256;
        int r = f >> 6, c4 = (f & 63) << 2;
        rb[i] = *(const float4*)(B + (size_t)r * N + bn + c4);
    }

    for (int k0 = 0; k0 < K; k0 += GBK) {
        // ---- store staged tile to smem (converted to tf32 bits) ----
        #pragma unroll
        for (int i = 0; i < 2; i++) {
            int f = tid + i * 256;
            int r = f >> 2, kc = (f & 3) << 2;
            As[r * AS_STRIDE + kc + 0] = __uint_as_float(f2tf(ra[i].x));
            As[r * AS_STRIDE + kc + 1] = __uint_as_float(f2tf(ra[i].y));
            As[r * AS_STRIDE + kc + 2] = __uint_as_float(f2tf(ra[i].z));
            As[r * AS_STRIDE + kc + 3] = __uint_as_float(f2tf(ra[i].w));
        }
        #pragma unroll
        for (int i = 0; i < 4; i++) {
            int f = tid + i * 256;
            int r = f >> 6, c4 = (f & 63) << 2;
            float4 v;
            v.x = __uint_as_float(f2tf(rb[i].x));
            v.y = __uint_as_float(f2tf(rb[i].y));
            v.z = __uint_as_float(f2tf(rb[i].z));
            v.w = __uint_as_float(f2tf(rb[i].w));
            *(float4*)&Bs[r * BS_STRIDE + c4] = v;
        }
        __syncthreads();

        // ---- prefetch next tile ----
        bool more = (k0 + GBK) < K;
        if (more) {
            int kn = k0 + GBK;
            #pragma unroll
            for (int i = 0; i < 2; i++) {
                int f = tid + i * 256;
                int r = f >> 2, kc = (f & 3) << 2;
                ra[i] = (bm + r < M) ? *(const float4*)(A + (size_t)(bm + r) * K + kn + kc)
                                     : make_float4(0.f, 0.f, 0.f, 0.f);
            }
            #pragma unroll
            for (int i = 0; i < 4; i++) {
                int f = tid + i * 256;
                int r = f >> 6, c4 = (f & 63) << 2;
                rb[i] = *(const float4*)(B + (size_t)(kn + r) * N + bn + c4);
            }
        }

        // ---- compute from smem ----
        #pragma unroll
        for (int kk = 0; kk < GBK; kk += 8) {
            uint32_t af[4][4], bf[8][2];
            #pragma unroll
            for (int i = 0; i < 4; i++) {
                int r0 = wm + i * 16 + gid;
                af[i][0] = __float_as_uint(As[(r0)     * AS_STRIDE + kk + tig]);
                af[i][1] = __float_as_uint(As[(r0 + 8) * AS_STRIDE + kk + tig]);
                af[i][2] = __float_as_uint(As[(r0)     * AS_STRIDE + kk + tig + 4]);
                af[i][3] = __float_as_uint(As[(r0 + 8) * AS_STRIDE + kk + tig + 4]);
            }
            #pragma unroll
            for (int j = 0; j < 8; j++) {
                int c0 = wn + j * 8 + gid;
                bf[j][0] = __float_as_uint(Bs[(kk + tig)     * BS_STRIDE + c0]);
                bf[j][1] = __float_as_uint(Bs[(kk + tig + 4) * BS_STRIDE + c0]);
            }
            #pragma unroll
            for (int i = 0; i < 4; i++)
                #pragma unroll
                for (int j = 0; j < 8; j++)
                    mma_tf32(acc[i][j], af[i], bf[j]);
        }
        __syncthreads();
    }

    // ---- epilogue: bias add + store ----
    #pragma unroll
    for (int i = 0; i < 4; i++) {
        int r0 = bm + wm + i * 16 + gid;
        #pragma unroll
        for (int j = 0; j < 8; j++) {
            int c = bn + wn + j * 8 + tig * 2;
            float2 bb = *(const float2*)(bias + c);
            if (r0 < M) {
                float2 o = make_float2(acc[i][j][0] + bb.x, acc[i][j][1] + bb.y);
                *(float2*)(C + (size_t)r0 * N + c) = o;
            }
            if (r0 + 8 < M) {
                float2 o = make_float2(acc[i][j][2] + bb.x, acc[i][j][3] + bb.y);
                *(float2*)(C + (size_t)(r0 + 8) * N + c) = o;
            }
        }
    }
}

// ---------------- edge attention: 1 block = 1 dst node, 1 warp = 1 head ----------------
__global__ __launch_bounds__(256)
void attn_kernel(const float* __restrict__ qkvs, const int* __restrict__ rowptr,
                 const int* __restrict__ col, float* __restrict__ attn) {
    int node = blockIdx.x;
    int wid  = threadIdx.x >> 5;   // head
    int lane = threadIdx.x & 31;
    const float scale = 0.0883883476483184f; // 1/sqrt(128)

    float4 q = *(const float4*)(qkvs + (size_t)node * QKVS_W + wid * CC + lane * 4);
    int e0 = rowptr[node], e1 = rowptr[node + 1];

    float m = -1e30f, den = 0.f;
    float4 acc = make_float4(0.f, 0.f, 0.f, 0.f);
    for (int e = e0; e < e1; e++) {
        int s = col[e];
        const float* base = qkvs + (size_t)s * QKVS_W + wid * CC + lane * 4;
        float4 kv = *(const float4*)(base + OFF_K);
        float d = q.x * kv.x + q.y * kv.y + q.z * kv.z + q.w * kv.w;
        #pragma unroll
        for (int off = 16; off; off >>= 1) d += __shfl_xor_sync(0xffffffffu, d, off);
        float logit = d * scale;
        float mn   = fmaxf(m, logit);
        float corr = __expf(m - mn);
        float p    = __expf(logit - mn);
        float4 vv = *(const float4*)(base + OFF_V);
        den   = den * corr + p;
        acc.x = acc.x * corr + p * vv.x;
        acc.y = acc.y * corr + p * vv.y;
        acc.z = acc.z * corr + p * vv.z;
        acc.w = acc.w * corr + p * vv.w;
        m = mn;
    }
    float inv = 1.f / (den + 1e-16f);
    __shared__ float sm[HH * CC];
    sm[wid * CC + lane * 4 + 0] = acc.x * inv;
    sm[wid * CC + lane * 4 + 1] = acc.y * inv;
    sm[wid * CC + lane * 4 + 2] = acc.z * inv;
    sm[wid * CC + lane * 4 + 3] = acc.w * inv;
    __syncthreads();
    if (threadIdx.x < CC) {
        float s = 0.f;
        #pragma unroll
        for (int h = 0; h < HH; h++) s += sm[h * CC + threadIdx.x];
        attn[(size_t)node * CC + threadIdx.x] = s * 0.125f;
    }
}

// ---------------- beta-gate + (residual) + LayerNorm + ReLU: 1 warp = 1 node ----------------
__global__ __launch_bounds__(256)
void gate_ln_kernel(const float* __restrict__ attn, const float* __restrict__ qkvs,
                    const float* __restrict__ Wb, const float* __restrict__ gam,
                    const float* __restrict__ bet, const float* __restrict__ res,
                    float* __restrict__ out, int N) {
    int node = blockIdx.x * 8 + (threadIdx.x >> 5);
    if (node >= N) return;
    int lane = threadIdx.x & 31;
    int c = lane * 4;

    float4 a  = *(const float4*)(attn + (size_t)node * CC + c);
    float4 xr = *(const float4*)(qkvs + (size_t)node * QKVS_W + OFF_S + c);
    float4 w0 = *(const float4*)(Wb + c);
    float4 w1 = *(const float4*)(Wb + 128 + c);
    float4 w2 = *(const float4*)(Wb + 256 + c);

    float t = a.x * w0.x + a.y * w0.y + a.z * w0.z + a.w * w0.w
            + xr.x * w1.x + xr.y * w1.y + xr.z * w1.z + xr.w * w1.w
            + (a.x - xr.x) * w2.x + (a.y - xr.y) * w2.y
            + (a.z - xr.z) * w2.z + (a.w - xr.w) * w2.w;
    #pragma unroll
    for (int off = 16; off; off >>= 1) t += __shfl_xor_sync(0xffffffffu, t, off);
    float beta = 1.f / (1.f + __expf(-t));

    float4 y;
    y.x = beta * xr.x + (1.f - beta) * a.x;
    y.y = beta * xr.y + (1.f - beta) * a.y;
    y.z = beta * xr.z + (1.f - beta) * a.z;
    y.w = beta * xr.w + (1.f - beta) * a.w;
    if (res) {
        float4 r = *(const float4*)(res + (size_t)node * CC + c);
        y.x += r.x; y.y += r.y; y.z += r.z; y.w += r.w;
    }
    float s = y.x + y.y + y.z + y.w;
    #pragma unroll
    for (int off = 16; off; off >>= 1) s += __shfl_xor_sync(0xffffffffu, s, off);
    float mu = s * (1.f / 128.f);
    float dx0 = y.x - mu, dx1 = y.y - mu, dx2 = y.z - mu, dx3 = y.w - mu;
    float q = dx0 * dx0 + dx1 * dx1 + dx2 * dx2 + dx3 * dx3;
    #pragma unroll
    for (int off = 16; off; off >>= 1) q += __shfl_xor_sync(0xffffffffu, q, off);
    float rstd = rsqrtf(q * (1.f / 128.f) + 1e-5f);
    float4 gg = *(const float4*)(gam + c);
    float4 bb = *(const float4*)(bet + c);
    float4 o;
    o.x = fmaxf(dx0 * rstd * gg.x + bb.x, 0.f);
    o.y = fmaxf(dx1 * rstd * gg.y + bb.y, 0.f);
    o.z = fmaxf(dx2 * rstd * gg.z + bb.z, 0.f);
    o.w = fmaxf(dx3 * rstd * gg.w + bb.w, 0.f);
    *(float4*)(out + (size_t)node * CC + c) = o;
}

// ---------------- pooling ----------------
__global__ void pool_kernel(const float* __restrict__ h, const int* __restrict__ batch,
                            float* __restrict__ psum, int N) {
    int idx = blockIdx.x * blockDim.x + threadIdx.x;
    if (idx >= N * CC) return;
    int n = idx >> 7, c = idx & 127;
    atomicAdd(&psum[batch[n] * CC + c], h[idx]);
}

__global__ void cnt_kernel(const int* __restrict__ batch, float* __restrict__ cnt, int N) {
    int n = blockIdx.x * blockDim.x + threadIdx.x;
    if (n < N) atomicAdd(&cnt[batch[n]], 1.0f);
}

// ---------------- classifier: 64 threads, 1 per graph ----------------
__global__ void cls_kernel(const float* __restrict__ psum, const float* __restrict__ cnt,
                           const float* __restrict__ Wc1, const float* __restrict__ bc1,
                           const float* __restrict__ Wc2, const float* __restrict__ bc2,
                           float* __restrict__ out) {
    int g = threadIdx.x;
    if (g >= NG) return;
    float invc = 1.f / fmaxf(cnt[g], 1.f);
    float pooled[CC];
    #pragma unroll 8
    for (int c = 0; c < CC; c++) pooled[c] = psum[g * CC + c] * invc;
    float r = bc2[0];
    for (int j = 0; j < 64; j++) {
        float z = bc1[j];
        #pragma unroll 8
        for (int c = 0; c < CC; c++) z += pooled[c] * Wc1[c * 64 + j];
        r += fmaxf(z, 0.f) * Wc2[j];
    }
    out[g] = r;
}

// ---------------- launch ----------------
extern "C" void kernel_launch(void* const* d_in, const int* in_sizes, int n_in,
                              void* d_out, int out_size) {
    const int N = NN, E = EE;
    const int*   x     = (const int*)d_in[0];
    const int*   ei    = (const int*)d_in[1];
    const int*   src   = ei;
    const int*   dst   = ei + E;
    const int*   batch = (const int*)d_in[2];
    const float* emb   = (const float*)d_in[3];

    const float *Wq0 = (const float*)d_in[4],  *bq0 = (const float*)d_in[5];
    const float *Wk0 = (const float*)d_in[6],  *bk0 = (const float*)d_in[7];
    const float *Wv0 = (const float*)d_in[8],  *bv0 = (const float*)d_in[9];
    const float *Ws0 = (const float*)d_in[10], *bs0 = (const float*)d_in[11];
    const float *Wb0 = (const float*)d_in[12];
    const float *g0  = (const float*)d_in[13], *be0 = (const float*)d_in[14];
    const float *Wq1 = (const float*)d_in[15], *bq1 = (const float*)d_in[16];
    const float *Wk1 = (const float*)d_in[17], *bk1 = (const float*)d_in[18];
    const float *Wv1 = (const float*)d_in[19], *bv1 = (const float*)d_in[20];
    const float *Ws1 = (const float*)d_in[21], *bs1 = (const float*)d_in[22];
    const float *Wb1 = (const float*)d_in[23];
    const float *g1  = (const float*)d_in[24], *be1 = (const float*)d_in[25];
    const float *Wc1 = (const float*)d_in[26], *bc1 = (const float*)d_in[27];
    const float *Wc2 = (const float*)d_in[28], *bc2 = (const float*)d_in[29];

    float *h, *qkvs, *attn, *h1, *h2, *Wcat, *bcat, *pool, *cnt;
    int *deg, *rowptr, *wofs, *col, *bsum, *bsum2;
    cudaGetSymbolAddress((void**)&h,      g_h);
    cudaGetSymbolAddress((void**)&qkvs,   g_qkvs);
    cudaGetSymbolAddress((void**)&attn,   g_attn);
    cudaGetSymbolAddress((void**)&h1,     g_h1);
    cudaGetSymbolAddress((void**)&h2,     g_h2);
    cudaGetSymbolAddress((void**)&Wcat,   g_Wcat);
    cudaGetSymbolAddress((void**)&bcat,   g_bcat);
    cudaGetSymbolAddress((void**)&pool,   g_pool);
    cudaGetSymbolAddress((void**)&cnt,    g_cnt);
    cudaGetSymbolAddress((void**)&deg,    g_deg);
    cudaGetSymbolAddress((void**)&rowptr, g_rowptr);
    cudaGetSymbolAddress((void**)&wofs,   g_wofs);
    cudaGetSymbolAddress((void**)&col,    g_col);
    cudaGetSymbolAddress((void**)&bsum,   g_bsum);
    cudaGetSymbolAddress((void**)&bsum2,  g_bsum2);

    const int NB = (N + 255) / 256;   // 196

    // CSR build (by dst)
    cudaMemsetAsync(deg, 0, N * sizeof(int));
    hist_kernel<<<(E + 255) / 256, 256>>>(dst, deg, E);
    scan_block_kernel<<<NB, 256>>>(deg, rowptr, bsum, N);
    scan_bsum_kernel<<<1, 256>>>(bsum, bsum2, NB);
    scan_add_kernel<<<NB, 256>>>(rowptr, bsum2, N);
    copyofs_kernel<<<(N + 255) / 256, 256>>>(rowptr, wofs, N);
    scatter_kernel<<<(E + 255) / 256, 256>>>(src, dst, wofs, col, E);

    // embedding
    embed_kernel<<<(N * (EMB / 4) + 255) / 256, 256>>>(x, emb, h, N);

    dim3 ggrid(QKVS_W / GBN, (N + GBM - 1) / GBM);   // (13, 391)

    // ---- layer 0 (K = 256) ----
    pack_kernel<<<(256 * QKVS_W + 255) / 256, 256>>>(Wq0, Wk0, Wv0, Ws0, bq0, bk0, bv0, bs0,
                                                     Wcat, bcat, 256);
    gemm_tf32_kernel<<<ggrid, 256>>>(h, Wcat, bcat, qkvs, N, QKVS_W, 256);
    attn_kernel<<<N, 256>>>(qkvs, rowptr, col, attn);
    gate_ln_kernel<<<(N + 7) / 8, 256>>>(attn, qkvs, Wb0, g0, be0, (const float*)nullptr, h1, N);

    // ---- layer 1 (K = 128, residual) ----
    pack_kernel<<<(128 * QKVS_W + 255) / 256, 256>>>(Wq1, Wk1, Wv1, Ws1, bq1, bk1, bv1, bs1,
                                                     Wcat, bcat, 128);
    gemm_tf32_kernel<<<ggrid, 256>>>(h1, Wcat, bcat, qkvs, N, QKVS_W, 128);
    attn_kernel<<<N, 256>>>(qkvs, rowptr, col, attn);
    gate_ln_kernel<<<(N + 7) / 8, 256>>>(attn, qkvs, Wb1, g1, be1, h1, h2, N);

    // ---- pool + classifier ----
    cudaMemsetAsync(pool, 0, NG * CC * sizeof(float));
    cudaMemsetAsync(cnt, 0, NG * sizeof(float));
    pool_kernel<<<(N * CC + 255) / 256, 256>>>(h2, batch, pool, N);
    cnt_kernel<<<(N + 255) / 256, 256>>>(batch, cnt, N);
    cls_kernel<<<1, 64>>>(pool, cnt, Wc1, bc1, Wc2, bc2, (float*)d_out);
}

// round 3
// speedup vs baseline: 2.1714x; 1.2162x over previous
#include <cuda_runtime.h>
#include <cuda_bf16.h>
#include <math.h>
#include <stdint.h>

// ---------------- problem constants ----------------
#define NN 50000
#define EE 400000
#define HH 8
#define CC 128
#define EMB 256
#define NG 64
#define QKVS_W 3328   // 1024 q + 1024 k + 1024 v + 128 skip
#define OFF_K 1024
#define OFF_V 2048
#define OFF_S 3072
#define KV_W 2048     // bf16 per node: 8 heads * 256 (k4/v4 interleaved per 4ch)

// ---------------- scratch ----------------
__device__ float g_h[(size_t)NN * EMB];
__device__ float g_qkvs[(size_t)NN * QKVS_W];    // only q ([0,1024)) and skip ([3072,3328)) valid
__device__ __nv_bfloat16 g_kv[(size_t)NN * KV_W];
__device__ float g_attn[(size_t)NN * CC];
__device__ float g_h1[(size_t)NN * CC];
__device__ float g_h2[(size_t)NN * CC];
__device__ float g_Wcat[(size_t)EMB * QKVS_W];
__device__ float g_bcat[QKVS_W];
__device__ float g_pool[NG * CC];
__device__ float g_cnt[NG];
__device__ int   g_deg[NN];
__device__ int   g_rowptr[NN + 1];
__device__ int   g_wofs[NN];
__device__ int   g_col[EE];
__device__ int   g_bsum[256];
__device__ int   g_bsum2[256];

// ---------------- CSR build ----------------
__global__ void hist_kernel(const int* __restrict__ dst, int* __restrict__ deg, int E) {
    int e = blockIdx.x * blockDim.x + threadIdx.x;
    if (e < E) atomicAdd(&deg[dst[e]], 1);
}

__global__ void scan_block_kernel(const int* __restrict__ deg, int* __restrict__ rowptr,
                                  int* __restrict__ bsum, int n) {
    __shared__ int s[256];
    int i = blockIdx.x * 256 + threadIdx.x;
    int v = (i < n) ? deg[i] : 0;
    s[threadIdx.x] = v;
    __syncthreads();
    #pragma unroll
    for (int off = 1; off < 256; off <<= 1) {
        int t = (threadIdx.x >= off) ? s[threadIdx.x - off] : 0;
        __syncthreads();
        s[threadIdx.x] += t;
        __syncthreads();
    }
    if (i < n) rowptr[i + 1] = s[threadIdx.x];
    if (threadIdx.x == 255) bsum[blockIdx.x] = s[255];
}

__global__ void scan_bsum_kernel(const int* __restrict__ bsum, int* __restrict__ bsum2, int nb) {
    __shared__ int s[256];
    int t = threadIdx.x;
    int v = (t < nb) ? bsum[t] : 0;
    s[t] = v;
    __syncthreads();
    #pragma unroll
    for (int off = 1; off < 256; off <<= 1) {
        int x = (t >= off) ? s[t - off] : 0;
        __syncthreads();
        s[t] += x;
        __syncthreads();
    }
    if (t < nb) bsum2[t] = s[t] - v;   // exclusive
}

__global__ void scan_add_kernel(int* __restrict__ rowptr, const int* __restrict__ bsum2, int n) {
    int i = blockIdx.x * 256 + threadIdx.x;
    if (i < n) rowptr[i + 1] += bsum2[blockIdx.x];
    if (i == 0) rowptr[0] = 0;
}

__global__ void copyofs_kernel(const int* __restrict__ rowptr, int* __restrict__ wofs, int n) {
    int i = blockIdx.x * blockDim.x + threadIdx.x;
    if (i < n) wofs[i] = rowptr[i];
}

__global__ void scatter_kernel(const int* __restrict__ src, const int* __restrict__ dst,
                               int* __restrict__ wofs, int* __restrict__ col, int E) {
    int e = blockIdx.x * blockDim.x + threadIdx.x;
    if (e < E) {
        int p = atomicAdd(&wofs[dst[e]], 1);
        col[p] = src[e];
    }
}

// ---------------- embedding gather ----------------
__global__ void embed_kernel(const int* __restrict__ x, const float* __restrict__ emb,
                             float* __restrict__ h, int N) {
    int idx = blockIdx.x * blockDim.x + threadIdx.x;
    if (idx >= N * (EMB / 4)) return;
    int n  = idx >> 6;
    int c4 = (idx & 63) << 2;
    *(float4*)(h + (size_t)n * EMB + c4) =
        *(const float4*)(emb + (size_t)x[n] * EMB + c4);
}

// ---------------- weight packing [K, 3328] ----------------
__global__ void pack_kernel(const float* __restrict__ Wq, const float* __restrict__ Wk,
                            const float* __restrict__ Wv, const float* __restrict__ Ws,
                            const float* __restrict__ bq, const float* __restrict__ bk,
                            const float* __restrict__ bv, const float* __restrict__ bs,
                            float* __restrict__ Wcat, float* __restrict__ bcat, int K) {
    int idx = blockIdx.x * blockDim.x + threadIdx.x;
    if (idx >= K * QKVS_W) return;
    int k = idx / QKVS_W, o = idx - k * QKVS_W;
    float v;
    if (o < 1024)      v = Wq[k * 1024 + o];
    else if (o < 2048) v = Wk[k * 1024 + (o - 1024)];
    else if (o < 3072) v = Wv[k * 1024 + (o - 2048)];
    else               v = Ws[k * 128  + (o - 3072)];
    Wcat[idx] = v;
    if (k == 0) {
        float b;
        if (o < 1024)      b = bq[o];
        else if (o < 2048) b = bk[o - 1024];
        else if (o < 3072) b = bv[o - 2048];
        else               b = bs[o - 3072];
        bcat[o] = b;
    }
}

// ---------------- TF32 tensor-core GEMM: 128x256x16 block, 8 warps of 64x64 ----------------
__device__ __forceinline__ uint32_t f2tf(float f) {
    uint32_t u;
    asm("cvt.rna.tf32.f32 %0, %1;" : "=r"(u) : "f"(f));
    return u;
}

__device__ __forceinline__ void mma_tf32(float* c, const uint32_t* a, const uint32_t* b) {
    asm volatile(
        "mma.sync.aligned.m16n8k8.row.col.f32.tf32.tf32.f32 "
        "{%0,%1,%2,%3}, {%4,%5,%6,%7}, {%8,%9}, {%0,%1,%2,%3};"
        : "+f"(c[0]), "+f"(c[1]), "+f"(c[2]), "+f"(c[3])
        : "r"(a[0]), "r"(a[1]), "r"(a[2]), "r"(a[3]), "r"(b[0]), "r"(b[1]));
}

#define GBM 128
#define GBN 256
#define GBK 16
#define AS_STRIDE 20
#define BS_STRIDE 264

// epilogue store: q & skip -> fp32 qkvs; k/v -> bf16 interleaved kv buffer
__device__ __forceinline__ void epi_store(float* __restrict__ C, __nv_bfloat16* __restrict__ kv,
                                          int r, int c, int N, float2 o) {
    if (c < OFF_K || c >= OFF_S) {
        *(float2*)(C + (size_t)r * N + c) = o;
    } else {
        bool isk = c < OFF_V;
        int ch = isk ? (c - OFF_K) : (c - OFF_V);
        int head = ch >> 7, within = ch & 127;
        int slot = head * 256 + (within >> 2) * 8 + (within & 3) + (isk ? 0 : 4);
        *(__nv_bfloat162*)(kv + (size_t)r * KV_W + slot) = __float22bfloat162_rn(o);
    }
}

__global__ __launch_bounds__(256, 1)
void gemm_tf32_kernel(const float* __restrict__ A, const float* __restrict__ B,
                      const float* __restrict__ bias, float* __restrict__ C,
                      __nv_bfloat16* __restrict__ kv,
                      int M, int N, int K) {
    __shared__ float As[GBM * AS_STRIDE];
    __shared__ float Bs[GBK * BS_STRIDE];

    int bm = blockIdx.y * GBM;
    int bn = blockIdx.x * GBN;
    int tid = threadIdx.x;
    int wid = tid >> 5, lane = tid & 31;
    int wm = (wid >> 2) * 64;
    int wn = (wid & 3) * 64;
    int gid = lane >> 2, tig = lane & 3;

    float acc[4][8][4];
    #pragma unroll
    for (int i = 0; i < 4; i++)
        #pragma unroll
        for (int j = 0; j < 8; j++)
            #pragma unroll
            for (int q = 0; q < 4; q++) acc[i][j][q] = 0.f;

    float4 ra[2], rb[4];

    #pragma unroll
    for (int i = 0; i < 2; i++) {
        int f = tid + i * 256;
        int r = f >> 2, kc = (f & 3) << 2;
        ra[i] = (bm + r < M) ? *(const float4*)(A + (size_t)(bm + r) * K + kc)
                             : make_float4(0.f, 0.f, 0.f, 0.f);
    }
    #pragma unroll
    for (int i = 0; i < 4; i++) {
        int f = tid + i * 256;
        int r = f >> 6, c4 = (f & 63) << 2;
        rb[i] = *(const float4*)(B + (size_t)r * N + bn + c4);
    }

    for (int k0 = 0; k0 < K; k0 += GBK) {
        #pragma unroll
        for (int i = 0; i < 2; i++) {
            int f = tid + i * 256;
            int r = f >> 2, kc = (f & 3) << 2;
            As[r * AS_STRIDE + kc + 0] = __uint_as_float(f2tf(ra[i].x));
            As[r * AS_STRIDE + kc + 1] = __uint_as_float(f2tf(ra[i].y));
            As[r * AS_STRIDE + kc + 2] = __uint_as_float(f2tf(ra[i].z));
            As[r * AS_STRIDE + kc + 3] = __uint_as_float(f2tf(ra[i].w));
        }
        #pragma unroll
        for (int i = 0; i < 4; i++) {
            int f = tid + i * 256;
            int r = f >> 6, c4 = (f & 63) << 2;
            float4 v;
            v.x = __uint_as_float(f2tf(rb[i].x));
            v.y = __uint_as_float(f2tf(rb[i].y));
            v.z = __uint_as_float(f2tf(rb[i].z));
            v.w = __uint_as_float(f2tf(rb[i].w));
            *(float4*)&Bs[r * BS_STRIDE + c4] = v;
        }
        __syncthreads();

        bool more = (k0 + GBK) < K;
        if (more) {
            int kn = k0 + GBK;
            #pragma unroll
            for (int i = 0; i < 2; i++) {
                int f = tid + i * 256;
                int r = f >> 2, kc = (f & 3) << 2;
                ra[i] = (bm + r < M) ? *(const float4*)(A + (size_t)(bm + r) * K + kn + kc)
                                     : make_float4(0.f, 0.f, 0.f, 0.f);
            }
            #pragma unroll
            for (int i = 0; i < 4; i++) {
                int f = tid + i * 256;
                int r = f >> 6, c4 = (f & 63) << 2;
                rb[i] = *(const float4*)(B + (size_t)(kn + r) * N + bn + c4);
            }
        }

        #pragma unroll
        for (int kk = 0; kk < GBK; kk += 8) {
            uint32_t af[4][4], bf[8][2];
            #pragma unroll
            for (int i = 0; i < 4; i++) {
                int r0 = wm + i * 16 + gid;
                af[i][0] = __float_as_uint(As[(r0)     * AS_STRIDE + kk + tig]);
                af[i][1] = __float_as_uint(As[(r0 + 8) * AS_STRIDE + kk + tig]);
                af[i][2] = __float_as_uint(As[(r0)     * AS_STRIDE + kk + tig + 4]);
                af[i][3] = __float_as_uint(As[(r0 + 8) * AS_STRIDE + kk + tig + 4]);
            }
            #pragma unroll
            for (int j = 0; j < 8; j++) {
                int c0 = wn + j * 8 + gid;
                bf[j][0] = __float_as_uint(Bs[(kk + tig)     * BS_STRIDE + c0]);
                bf[j][1] = __float_as_uint(Bs[(kk + tig + 4) * BS_STRIDE + c0]);
            }
            #pragma unroll
            for (int i = 0; i < 4; i++)
                #pragma unroll
                for (int j = 0; j < 8; j++)
                    mma_tf32(acc[i][j], af[i], bf[j]);
        }
        __syncthreads();
    }

    #pragma unroll
    for (int i = 0; i < 4; i++) {
        int r0 = bm + wm + i * 16 + gid;
        #pragma unroll
        for (int j = 0; j < 8; j++) {
            int c = bn + wn + j * 8 + tig * 2;
            float2 bb = *(const float2*)(bias + c);
            if (r0 < M)
                epi_store(C, kv, r0, c, N, make_float2(acc[i][j][0] + bb.x, acc[i][j][1] + bb.y));
            if (r0 + 8 < M)
                epi_store(C, kv, r0 + 8, c, N, make_float2(acc[i][j][2] + bb.x, acc[i][j][3] + bb.y));
        }
    }
}

// ---------------- edge attention: 1 block = 1 dst node, 1 warp = 1 head ----------------
__global__ __launch_bounds__(256)
void attn_kernel(const float* __restrict__ qkvs, const __nv_bfloat16* __restrict__ kv,
                 const int* __restrict__ rowptr, const int* __restrict__ col,
                 float* __restrict__ attn) {
    int node = blockIdx.x;
    int wid  = threadIdx.x >> 5;   // head
    int lane = threadIdx.x & 31;
    const float scale = 0.0883883476483184f; // 1/sqrt(128)

    float4 q = *(const float4*)(qkvs + (size_t)node * QKVS_W + wid * CC + lane * 4);
    int e0 = rowptr[node], e1 = rowptr[node + 1];

    float m = -1e30f, den = 0.f;
    float4 acc = make_float4(0.f, 0.f, 0.f, 0.f);
    for (int e = e0; e < e1; e++) {
        int s = col[e];
        // one 16B load: [k0 k1 k2 k3 v0 v1 v2 v3] bf16
        uint4 pk = *(const uint4*)(kv + (size_t)s * KV_W + wid * 256 + lane * 8);
        float2 k01 = __bfloat1622float2(*(const __nv_bfloat162*)&pk.x);
        float2 k23 = __bfloat1622float2(*(const __nv_bfloat162*)&pk.y);
        float2 v01 = __bfloat1622float2(*(const __nv_bfloat162*)&pk.z);
        float2 v23 = __bfloat1622float2(*(const __nv_bfloat162*)&pk.w);
        float d = q.x * k01.x + q.y * k01.y + q.z * k23.x + q.w * k23.y;
        #pragma unroll
        for (int off = 16; off; off >>= 1) d += __shfl_xor_sync(0xffffffffu, d, off);
        float logit = d * scale;
        float mn   = fmaxf(m, logit);
        float corr = __expf(m - mn);
        float p    = __expf(logit - mn);
        den   = den * corr + p;
        acc.x = acc.x * corr + p * v01.x;
        acc.y = acc.y * corr + p * v01.y;
        acc.z = acc.z * corr + p * v23.x;
        acc.w = acc.w * corr + p * v23.y;
        m = mn;
    }
    float inv = 1.f / (den + 1e-16f);
    __shared__ float sm[HH * CC];
    sm[wid * CC + lane * 4 + 0] = acc.x * inv;
    sm[wid * CC + lane * 4 + 1] = acc.y * inv;
    sm[wid * CC + lane * 4 + 2] = acc.z * inv;
    sm[wid * CC + lane * 4 + 3] = acc.w * inv;
    __syncthreads();
    if (threadIdx.x < CC) {
        float s = 0.f;
        #pragma unroll
        for (int h = 0; h < HH; h++) s += sm[h * CC + threadIdx.x];
        attn[(size_t)node * CC + threadIdx.x] = s * 0.125f;
    }
}

// ---------------- beta-gate + (residual) + LayerNorm + ReLU ----------------
__global__ __launch_bounds__(256)
void gate_ln_kernel(const float* __restrict__ attn, const float* __restrict__ qkvs,
                    const float* __restrict__ Wb, const float* __restrict__ gam,
                    const float* __restrict__ bet, const float* __restrict__ res,
                    float* __restrict__ out, int N) {
    int node = blockIdx.x * 8 + (threadIdx.x >> 5);
    if (node >= N) return;
    int lane = threadIdx.x & 31;
    int c = lane * 4;

    float4 a  = *(const float4*)(attn + (size_t)node * CC + c);
    float4 xr = *(const float4*)(qkvs + (size_t)node * QKVS_W + OFF_S + c);
    float4 w0 = *(const float4*)(Wb + c);
    float4 w1 = *(const float4*)(Wb + 128 + c);
    float4 w2 = *(const float4*)(Wb + 256 + c);

    float t = a.x * w0.x + a.y * w0.y + a.z * w0.z + a.w * w0.w
            + xr.x * w1.x + xr.y * w1.y + xr.z * w1.z + xr.w * w1.w
            + (a.x - xr.x) * w2.x + (a.y - xr.y) * w2.y
            + (a.z - xr.z) * w2.z + (a.w - xr.w) * w2.w;
    #pragma unroll
    for (int off = 16; off; off >>= 1) t += __shfl_xor_sync(0xffffffffu, t, off);
    float beta = 1.f / (1.f + __expf(-t));

    float4 y;
    y.x = beta * xr.x + (1.f - beta) * a.x;
    y.y = beta * xr.y + (1.f - beta) * a.y;
    y.z = beta * xr.z + (1.f - beta) * a.z;
    y.w = beta * xr.w + (1.f - beta) * a.w;
    if (res) {
        float4 r = *(const float4*)(res + (size_t)node * CC + c);
        y.x += r.x; y.y += r.y; y.z += r.z; y.w += r.w;
    }
    float s = y.x + y.y + y.z + y.w;
    #pragma unroll
    for (int off = 16; off; off >>= 1) s += __shfl_xor_sync(0xffffffffu, s, off);
    float mu = s * (1.f / 128.f);
    float dx0 = y.x - mu, dx1 = y.y - mu, dx2 = y.z - mu, dx3 = y.w - mu;
    float q = dx0 * dx0 + dx1 * dx1 + dx2 * dx2 + dx3 * dx3;
    #pragma unroll
    for (int off = 16; off; off >>= 1) q += __shfl_xor_sync(0xffffffffu, q, off);
    float rstd = rsqrtf(q * (1.f / 128.f) + 1e-5f);
    float4 gg = *(const float4*)(gam + c);
    float4 bb = *(const float4*)(bet + c);
    float4 o;
    o.x = fmaxf(dx0 * rstd * gg.x + bb.x, 0.f);
    o.y = fmaxf(dx1 * rstd * gg.y + bb.y, 0.f);
    o.z = fmaxf(dx2 * rstd * gg.z + bb.z, 0.f);
    o.w = fmaxf(dx3 * rstd * gg.w + bb.w, 0.f);
    *(float4*)(out + (size_t)node * CC + c) = o;
}

// ---------------- pooling: batch is SORTED -> segmented running sums ----------------
// block = 128 threads (one per channel), covers 64 consecutive nodes
__global__ __launch_bounds__(128)
void pool_kernel(const float* __restrict__ h, const int* __restrict__ batch,
                 float* __restrict__ psum, float* __restrict__ cnt, int N) {
    int c = threadIdx.x;
    int n0 = blockIdx.x * 64;
    int n1 = min(n0 + 64, N);
    int cur = batch[n0];
    float s = 0.f;
    float k = 0.f;
    for (int n = n0; n < n1; n++) {
        int b = batch[n];
        if (b != cur) {
            atomicAdd(&psum[cur * CC + c], s);
            if (c == 0) atomicAdd(&cnt[cur], k);
            s = 0.f; k = 0.f; cur = b;
        }
        s += h[(size_t)n * CC + c];
        k += 1.f;
    }
    atomicAdd(&psum[cur * CC + c], s);
    if (c == 0) atomicAdd(&cnt[cur], k);
}

// ---------------- classifier ----------------
__global__ void cls_kernel(const float* __restrict__ psum, const float* __restrict__ cnt,
                           const float* __restrict__ Wc1, const float* __restrict__ bc1,
                           const float* __restrict__ Wc2, const float* __restrict__ bc2,
                           float* __restrict__ out) {
    int g = threadIdx.x;
    if (g >= NG) return;
    float invc = 1.f / fmaxf(cnt[g], 1.f);
    float pooled[CC];
    #pragma unroll 8
    for (int c = 0; c < CC; c++) pooled[c] = psum[g * CC + c] * invc;
    float r = bc2[0];
    for (int j = 0; j < 64; j++) {
        float z = bc1[j];
        #pragma unroll 8
        for (int c = 0; c < CC; c++) z += pooled[c] * Wc1[c * 64 + j];
        r += fmaxf(z, 0.f) * Wc2[j];
    }
    out[g] = r;
}

// ---------------- launch ----------------
extern "C" void kernel_launch(void* const* d_in, const int* in_sizes, int n_in,
                              void* d_out, int out_size) {
    const int N = NN, E = EE;
    const int*   x     = (const int*)d_in[0];
    const int*   ei    = (const int*)d_in[1];
    const int*   src   = ei;
    const int*   dst   = ei + E;
    const int*   batch = (const int*)d_in[2];
    const float* emb   = (const float*)d_in[3];

    const float *Wq0 = (const float*)d_in[4],  *bq0 = (const float*)d_in[5];
    const float *Wk0 = (const float*)d_in[6],  *bk0 = (const float*)d_in[7];
    const float *Wv0 = (const float*)d_in[8],  *bv0 = (const float*)d_in[9];
    const float *Ws0 = (const float*)d_in[10], *bs0 = (const float*)d_in[11];
    const float *Wb0 = (const float*)d_in[12];
    const float *g0  = (const float*)d_in[13], *be0 = (const float*)d_in[14];
    const float *Wq1 = (const float*)d_in[15], *bq1 = (const float*)d_in[16];
    const float *Wk1 = (const float*)d_in[17], *bk1 = (const float*)d_in[18];
    const float *Wv1 = (const float*)d_in[19], *bv1 = (const float*)d_in[20];
    const float *Ws1 = (const float*)d_in[21], *bs1 = (const float*)d_in[22];
    const float *Wb1 = (const float*)d_in[23];
    const float *g1  = (const float*)d_in[24], *be1 = (const float*)d_in[25];
    const float *Wc1 = (const float*)d_in[26], *bc1 = (const float*)d_in[27];
    const float *Wc2 = (const float*)d_in[28], *bc2 = (const float*)d_in[29];

    float *h, *qkvs, *attn, *h1, *h2, *Wcat, *bcat, *pool, *cnt;
    __nv_bfloat16 *kv;
    int *deg, *rowptr, *wofs, *col, *bsum, *bsum2;
    cudaGetSymbolAddress((void**)&h,      g_h);
    cudaGetSymbolAddress((void**)&qkvs,   g_qkvs);
    cudaGetSymbolAddress((void**)&kv,     g_kv);
    cudaGetSymbolAddress((void**)&attn,   g_attn);
    cudaGetSymbolAddress((void**)&h1,     g_h1);
    cudaGetSymbolAddress((void**)&h2,     g_h2);
    cudaGetSymbolAddress((void**)&Wcat,   g_Wcat);
    cudaGetSymbolAddress((void**)&bcat,   g_bcat);
    cudaGetSymbolAddress((void**)&pool,   g_pool);
    cudaGetSymbolAddress((void**)&cnt,    g_cnt);
    cudaGetSymbolAddress((void**)&deg,    g_deg);
    cudaGetSymbolAddress((void**)&rowptr, g_rowptr);
    cudaGetSymbolAddress((void**)&wofs,   g_wofs);
    cudaGetSymbolAddress((void**)&col,    g_col);
    cudaGetSymbolAddress((void**)&bsum,   g_bsum);
    cudaGetSymbolAddress((void**)&bsum2,  g_bsum2);

    const int NB = (N + 255) / 256;

    // CSR build (by dst)
    cudaMemsetAsync(deg, 0, N * sizeof(int));
    hist_kernel<<<(E + 255) / 256, 256>>>(dst, deg, E);
    scan_block_kernel<<<NB, 256>>>(deg, rowptr, bsum, N);
    scan_bsum_kernel<<<1, 256>>>(bsum, bsum2, NB);
    scan_add_kernel<<<NB, 256>>>(rowptr, bsum2, N);
    copyofs_kernel<<<(N + 255) / 256, 256>>>(rowptr, wofs, N);
    scatter_kernel<<<(E + 255) / 256, 256>>>(src, dst, wofs, col, E);

    // embedding
    embed_kernel<<<(N * (EMB / 4) + 255) / 256, 256>>>(x, emb, h, N);

    dim3 ggrid(QKVS_W / GBN, (N + GBM - 1) / GBM);

    // ---- layer 0 (K = 256) ----
    pack_kernel<<<(256 * QKVS_W + 255) / 256, 256>>>(Wq0, Wk0, Wv0, Ws0, bq0, bk0, bv0, bs0,
                                                     Wcat, bcat, 256);
    gemm_tf32_kernel<<<ggrid, 256>>>(h, Wcat, bcat, qkvs, kv, N, QKVS_W, 256);
    attn_kernel<<<N, 256>>>(qkvs, kv, rowptr, col, attn);
    gate_ln_kernel<<<(N + 7) / 8, 256>>>(attn, qkvs, Wb0, g0, be0, (const float*)nullptr, h1, N);

    // ---- layer 1 (K = 128, residual) ----
    pack_kernel<<<(128 * QKVS_W + 255) / 256, 256>>>(Wq1, Wk1, Wv1, Ws1, bq1, bk1, bv1, bs1,
                                                     Wcat, bcat, 128);
    gemm_tf32_kernel<<<ggrid, 256>>>(h1, Wcat, bcat, qkvs, kv, N, QKVS_W, 128);
    attn_kernel<<<N, 256>>>(qkvs, kv, rowptr, col, attn);
    gate_ln_kernel<<<(N + 7) / 8, 256>>>(attn, qkvs, Wb1, g1, be1, h1, h2, N);

    // ---- pool + classifier ----
    cudaMemsetAsync(pool, 0, NG * CC * sizeof(float));
    cudaMemsetAsync(cnt, 0, NG * sizeof(float));
    pool_kernel<<<(N + 63) / 64, 128>>>(h2, batch, pool, cnt, N);
    cls_kernel<<<1, 64>>>(pool, cnt, Wc1, bc1, Wc2, bc2, (float*)d_out);
}

// round 5
// speedup vs baseline: 2.4407x; 1.1240x over previous
#include <cuda_runtime.h>
#include <cuda_bf16.h>
#include <math.h>
#include <stdint.h>

// ---------------- problem constants ----------------
#define NN 50000
#define EE 400000
#define HH 8
#define CC 128
#define EMB 256
#define NG 64
#define NOUT 3328     // padded: 1024 q + 1024 k + 1024 v + 128 skip + 128 zero-pad
#define NREAL 3200    // real columns; [3200,3328) are zero padding, dropped in epilogue
#define OFF_K 1024
#define OFF_V 2048
#define OFF_S 3072
#define KV_W 2048     // bf16 per node: 8 heads * 256 (k4/v4 interleaved per 4ch)
#define QB_W 1024     // bf16 q per node

// ---------------- scratch ----------------
__device__ __nv_bfloat16 g_hb[(size_t)NN * EMB];    // layer0 GEMM A (bf16)
__device__ __nv_bfloat16 g_qb[(size_t)NN * QB_W];   // q (bf16)
__device__ __nv_bfloat16 g_kv[(size_t)NN * KV_W];   // k/v interleaved (bf16)
__device__ float g_skip[(size_t)NN * CC];           // skip proj (fp32, dense)
__device__ float g_attn[(size_t)NN * CC];
__device__ __nv_bfloat16 g_h1[(size_t)NN * CC];     // layer0 out (bf16)
__device__ __nv_bfloat16 g_h2[(size_t)NN * CC];     // layer1 out (bf16)
__device__ __nv_bfloat16 g_Wt[(size_t)NOUT * EMB];  // packed transposed weights bf16 [n][k]
__device__ float g_bcat[NOUT];
__device__ float g_pool[NG * CC];
__device__ float g_cnt[NG];
__device__ int   g_deg[NN];
__device__ int   g_rowptr[NN + 1];
__device__ int   g_wofs[NN];
__device__ int   g_col[EE];
__device__ int   g_bsum[256];
__device__ int   g_bsum2[256];

// ---------------- CSR build ----------------
__global__ void hist_kernel(const int* __restrict__ dst, int* __restrict__ deg, int E) {
    int e = blockIdx.x * blockDim.x + threadIdx.x;
    if (e < E) atomicAdd(&deg[dst[e]], 1);
}

__global__ void scan_block_kernel(const int* __restrict__ deg, int* __restrict__ rowptr,
                                  int* __restrict__ bsum, int n) {
    __shared__ int s[256];
    int i = blockIdx.x * 256 + threadIdx.x;
    int v = (i < n) ? deg[i] : 0;
    s[threadIdx.x] = v;
    __syncthreads();
    #pragma unroll
    for (int off = 1; off < 256; off <<= 1) {
        int t = (threadIdx.x >= off) ? s[threadIdx.x - off] : 0;
        __syncthreads();
        s[threadIdx.x] += t;
        __syncthreads();
    }
    if (i < n) rowptr[i + 1] = s[threadIdx.x];
    if (threadIdx.x == 255) bsum[blockIdx.x] = s[255];
}

__global__ void scan_bsum_kernel(const int* __restrict__ bsum, int* __restrict__ bsum2, int nb) {
    __shared__ int s[256];
    int t = threadIdx.x;
    int v = (t < nb) ? bsum[t] : 0;
    s[t] = v;
    __syncthreads();
    #pragma unroll
    for (int off = 1; off < 256; off <<= 1) {
        int x = (t >= off) ? s[t - off] : 0;
        __syncthreads();
        s[t] += x;
        __syncthreads();
    }
    if (t < nb) bsum2[t] = s[t] - v;   // exclusive
}

__global__ void scan_add_kernel(int* __restrict__ rowptr, const int* __restrict__ bsum2, int n) {
    int i = blockIdx.x * 256 + threadIdx.x;
    if (i < n) rowptr[i + 1] += bsum2[blockIdx.x];
    if (i == 0) rowptr[0] = 0;
}

__global__ void copyofs_kernel(const int* __restrict__ rowptr, int* __restrict__ wofs, int n) {
    int i = blockIdx.x * blockDim.x + threadIdx.x;
    if (i < n) wofs[i] = rowptr[i];
}

__global__ void scatter_kernel(const int* __restrict__ src, const int* __restrict__ dst,
                               int* __restrict__ wofs, int* __restrict__ col, int E) {
    int e = blockIdx.x * blockDim.x + threadIdx.x;
    if (e < E) {
        int p = atomicAdd(&wofs[dst[e]], 1);
        col[p] = src[e];
    }
}

// ---------------- embedding gather (fp32 -> bf16) ----------------
__global__ void embed_kernel(const int* __restrict__ x, const float* __restrict__ emb,
                             __nv_bfloat16* __restrict__ hb, int N) {
    int idx = blockIdx.x * blockDim.x + threadIdx.x;     // N * 32 threads, 8 elems each
    if (idx >= N * 32) return;
    int n  = idx >> 5;
    int g8 = (idx & 31) << 3;
    const float* p = emb + (size_t)x[n] * EMB + g8;
    float4 a = *(const float4*)p;
    float4 b = *(const float4*)(p + 4);
    __nv_bfloat162 o[4];
    o[0] = __float22bfloat162_rn(make_float2(a.x, a.y));
    o[1] = __float22bfloat162_rn(make_float2(a.z, a.w));
    o[2] = __float22bfloat162_rn(make_float2(b.x, b.y));
    o[3] = __float22bfloat162_rn(make_float2(b.z, b.w));
    *(uint4*)(hb + (size_t)n * EMB + g8) = *(uint4*)o;
}

// ---------------- weight pack+transpose: Wt[n][k] bf16, bcat fp32 ----------------
__global__ void pack_kernel(const float* __restrict__ Wq, const float* __restrict__ Wk,
                            const float* __restrict__ Wv, const float* __restrict__ Ws,
                            const float* __restrict__ bq, const float* __restrict__ bk,
                            const float* __restrict__ bv, const float* __restrict__ bs,
                            __nv_bfloat16* __restrict__ Wt, float* __restrict__ bcat,
                            int K, int lgK) {
    int idx = blockIdx.x * blockDim.x + threadIdx.x;
    if (idx >= NOUT * K) return;
    int k = idx & (K - 1), n = idx >> lgK;
    float v;
    if (n < 1024)       v = Wq[k * 1024 + n];
    else if (n < 2048)  v = Wk[k * 1024 + (n - 1024)];
    else if (n < 3072)  v = Wv[k * 1024 + (n - 2048)];
    else if (n < NREAL) v = Ws[k * 128  + (n - 3072)];
    else                v = 0.f;                      // zero padding columns
    Wt[(size_t)n * K + k] = __float2bfloat16(v);
    if (k == 0) {
        float b;
        if (n < 1024)       b = bq[n];
        else if (n < 2048)  b = bk[n - 1024];
        else if (n < 3072)  b = bv[n - 2048];
        else if (n < NREAL) b = bs[n - 3072];
        else                b = 0.f;
        bcat[n] = b;
    }
}

// ---------------- bf16 tensor-core GEMM: 128x256x32 block, 8 warps of 64x64 ----------------
__device__ __forceinline__ void mma_bf16(float* c, const uint32_t* a, const uint32_t* b) {
    asm volatile(
        "mma.sync.aligned.m16n8k16.row.col.f32.bf16.bf16.f32 "
        "{%0,%1,%2,%3}, {%4,%5,%6,%7}, {%8,%9}, {%0,%1,%2,%3};"
        : "+f"(c[0]), "+f"(c[1]), "+f"(c[2]), "+f"(c[3])
        : "r"(a[0]), "r"(a[1]), "r"(a[2]), "r"(a[3]), "r"(b[0]), "r"(b[1]));
}

#define GBM 128
#define GBN 256
#define GBK 32
#define AS2 20   // u32 (bf16-pair) stride per A row: 16 pairs + 4 pad
#define BS2 20   // u32 stride per B n-row

// epilogue router: q -> bf16 qb, k/v -> bf16 interleaved kv, skip -> fp32 dense, pad -> drop
__device__ __forceinline__ void epi_store(__nv_bfloat16* __restrict__ qb,
                                          __nv_bfloat16* __restrict__ kv,
                                          float* __restrict__ skip,
                                          int r, int c, float2 o) {
    if (c < OFF_K) {
        *(__nv_bfloat162*)(qb + (size_t)r * QB_W + c) = __float22bfloat162_rn(o);
    } else if (c < OFF_S) {
        bool isk = c < OFF_V;
        int ch = isk ? (c - OFF_K) : (c - OFF_V);
        int head = ch >> 7, within = ch & 127;
        int slot = head * 256 + (within >> 2) * 8 + (within & 3) + (isk ? 0 : 4);
        *(__nv_bfloat162*)(kv + (size_t)r * KV_W + slot) = __float22bfloat162_rn(o);
    } else if (c < NREAL) {
        *(float2*)(skip + (size_t)r * CC + (c - OFF_S)) = o;
    }
    // c >= NREAL: padding columns, dropped
}

__global__ __launch_bounds__(256, 1)
void gemm_bf16_kernel(const __nv_bfloat16* __restrict__ A, const __nv_bfloat16* __restrict__ Bt,
                      const float* __restrict__ bias,
                      __nv_bfloat16* __restrict__ qb, __nv_bfloat16* __restrict__ kv,
                      float* __restrict__ skip, int M, int K) {
    __shared__ uint32_t As[GBM * AS2];   // 10 KB
    __shared__ uint32_t Bs[GBN * BS2];   // 20 KB

    int bm = blockIdx.y * GBM;
    int bn = blockIdx.x * GBN;
    int tid = threadIdx.x;
    int wid = tid >> 5, lane = tid & 31;
    int wm = (wid >> 2) * 64;
    int wn = (wid & 3) * 64;
    int gid = lane >> 2, tig = lane & 3;

    float acc[4][8][4];
    #pragma unroll
    for (int i = 0; i < 4; i++)
        #pragma unroll
        for (int j = 0; j < 8; j++)
            #pragma unroll
            for (int q = 0; q < 4; q++) acc[i][j][q] = 0.f;

    int ar = tid >> 1, ap = tid & 1;
    uint4 ra[2], rb[4];
    const uint4 z4 = make_uint4(0u, 0u, 0u, 0u);
    {
        bool av = (bm + ar) < M;
        const __nv_bfloat16* ab = A + (size_t)(bm + ar) * K + ap * 16;
        ra[0] = av ? *(const uint4*)(ab)     : z4;
        ra[1] = av ? *(const uint4*)(ab + 8) : z4;
        const __nv_bfloat16* bb = Bt + (size_t)(bn + tid) * K;
        #pragma unroll
        for (int i = 0; i < 4; i++) rb[i] = *(const uint4*)(bb + i * 8);
    }

    for (int k0 = 0; k0 < K; k0 += GBK) {
        *(uint4*)&As[ar * AS2 + ap * 8 + 0] = ra[0];
        *(uint4*)&As[ar * AS2 + ap * 8 + 4] = ra[1];
        #pragma unroll
        for (int i = 0; i < 4; i++)
            *(uint4*)&Bs[tid * BS2 + i * 4] = rb[i];
        __syncthreads();

        if (k0 + GBK < K) {
            int kn = k0 + GBK;
            bool av = (bm + ar) < M;
            const __nv_bfloat16* ab = A + (size_t)(bm + ar) * K + kn + ap * 16;
            ra[0] = av ? *(const uint4*)(ab)     : z4;
            ra[1] = av ? *(const uint4*)(ab + 8) : z4;
            const __nv_bfloat16* bb = Bt + (size_t)(bn + tid) * K + kn;
            #pragma unroll
            for (int i = 0; i < 4; i++) rb[i] = *(const uint4*)(bb + i * 8);
        }

        #pragma unroll
        for (int kk2 = 0; kk2 < 16; kk2 += 8) {
            uint32_t af[4][4], bf[8][2];
            #pragma unroll
            for (int i = 0; i < 4; i++) {
                int r0 = wm + i * 16 + gid;
                af[i][0] = As[(r0)     * AS2 + kk2 + tig];
                af[i][1] = As[(r0 + 8) * AS2 + kk2 + tig];
                af[i][2] = As[(r0)     * AS2 + kk2 + tig + 4];
                af[i][3] = As[(r0 + 8) * AS2 + kk2 + tig + 4];
            }
            #pragma unroll
            for (int j = 0; j < 8; j++) {
                int n0 = wn + j * 8 + gid;
                bf[j][0] = Bs[n0 * BS2 + kk2 + tig];
                bf[j][1] = Bs[n0 * BS2 + kk2 + tig + 4];
            }
            #pragma unroll
            for (int i = 0; i < 4; i++)
                #pragma unroll
                for (int j = 0; j < 8; j++)
                    mma_bf16(acc[i][j], af[i], bf[j]);
        }
        __syncthreads();
    }

    #pragma unroll
    for (int i = 0; i < 4; i++) {
        int r0 = bm + wm + i * 16 + gid;
        #pragma unroll
        for (int j = 0; j < 8; j++) {
            int c = bn + wn + j * 8 + tig * 2;
            float2 bb = *(const float2*)(bias + c);
            if (r0 < M)
                epi_store(qb, kv, skip, r0, c,
                          make_float2(acc[i][j][0] + bb.x, acc[i][j][1] + bb.y));
            if (r0 + 8 < M)
                epi_store(qb, kv, skip, r0 + 8, c,
                          make_float2(acc[i][j][2] + bb.x, acc[i][j][3] + bb.y));
        }
    }
}

// ---------------- edge attention: 1 block = 1 node, 1 warp = 1 head, ILP x2 ----------------
__global__ __launch_bounds__(256)
void attn_kernel(const __nv_bfloat16* __restrict__ qb, const __nv_bfloat16* __restrict__ kv,
                 const int* __restrict__ rowptr, const int* __restrict__ col,
                 float* __restrict__ attn) {
    int node = blockIdx.x;
    int wid  = threadIdx.x >> 5;   // head
    int lane = threadIdx.x & 31;
    const float scale = 0.0883883476483184f; // 1/sqrt(128)

    uint2 qr = *(const uint2*)(qb + (size_t)node * QB_W + wid * CC + lane * 4);
    float2 qa = __bfloat1622float2(*(const __nv_bfloat162*)&qr.x);
    float2 qc = __bfloat1622float2(*(const __nv_bfloat162*)&qr.y);
    int e0 = rowptr[node], e1 = rowptr[node + 1];
    size_t off = (size_t)wid * 256 + lane * 8;

    float m0 = -1e30f, den0 = 0.f, m1 = -1e30f, den1 = 0.f;
    float4 a0 = make_float4(0.f, 0.f, 0.f, 0.f);
    float4 a1 = make_float4(0.f, 0.f, 0.f, 0.f);

    int e = e0;
    for (; e + 1 < e1; e += 2) {
        int s0 = col[e], s1 = col[e + 1];
        uint4 p0 = *(const uint4*)(kv + (size_t)s0 * KV_W + off);
        uint4 p1 = *(const uint4*)(kv + (size_t)s1 * KV_W + off);
        float2 k0a = __bfloat1622float2(*(const __nv_bfloat162*)&p0.x);
        float2 k0b = __bfloat1622float2(*(const __nv_bfloat162*)&p0.y);
        float2 k1a = __bfloat1622float2(*(const __nv_bfloat162*)&p1.x);
        float2 k1b = __bfloat1622float2(*(const __nv_bfloat162*)&p1.y);
        float d0 = qa.x * k0a.x + qa.y * k0a.y + qc.x * k0b.x + qc.y * k0b.y;
        float d1 = qa.x * k1a.x + qa.y * k1a.y + qc.x * k1b.x + qc.y * k1b.y;
        #pragma unroll
        for (int o = 16; o; o >>= 1) {
            d0 += __shfl_xor_sync(0xffffffffu, d0, o);
            d1 += __shfl_xor_sync(0xffffffffu, d1, o);
        }
        float2 v0a = __bfloat1622float2(*(const __nv_bfloat162*)&p0.z);
        float2 v0b = __bfloat1622float2(*(const __nv_bfloat162*)&p0.w);
        float2 v1a = __bfloat1622float2(*(const __nv_bfloat162*)&p1.z);
        float2 v1b = __bfloat1622float2(*(const __nv_bfloat162*)&p1.w);
        {
            float lg = d0 * scale;
            float mn = fmaxf(m0, lg);
            float cr = __expf(m0 - mn), p = __expf(lg - mn);
            den0 = den0 * cr + p;
            a0.x = a0.x * cr + p * v0a.x; a0.y = a0.y * cr + p * v0a.y;
            a0.z = a0.z * cr + p * v0b.x; a0.w = a0.w * cr + p * v0b.y;
            m0 = mn;
        }
        {
            float lg = d1 * scale;
            float mn = fmaxf(m1, lg);
            float cr = __expf(m1 - mn), p = __expf(lg - mn);
            den1 = den1 * cr + p;
            a1.x = a1.x * cr + p * v1a.x; a1.y = a1.y * cr + p * v1a.y;
            a1.z = a1.z * cr + p * v1b.x; a1.w = a1.w * cr + p * v1b.y;
            m1 = mn;
        }
    }
    if (e < e1) {
        int s0 = col[e];
        uint4 p0 = *(const uint4*)(kv + (size_t)s0 * KV_W + off);
        float2 k0a = __bfloat1622float2(*(const __nv_bfloat162*)&p0.x);
        float2 k0b = __bfloat1622float2(*(const __nv_bfloat162*)&p0.y);
        float d0 = qa.x * k0a.x + qa.y * k0a.y + qc.x * k0b.x + qc.y * k0b.y;
        #pragma unroll
        for (int o = 16; o; o >>= 1) d0 += __shfl_xor_sync(0xffffffffu, d0, o);
        float2 v0a = __bfloat1622float2(*(const __nv_bfloat162*)&p0.z);
        float2 v0b = __bfloat1622float2(*(const __nv_bfloat162*)&p0.w);
        float lg = d0 * scale;
        float mn = fmaxf(m0, lg);
        float cr = __expf(m0 - mn), p = __expf(lg - mn);
        den0 = den0 * cr + p;
        a0.x = a0.x * cr + p * v0a.x; a0.y = a0.y * cr + p * v0a.y;
        a0.z = a0.z * cr + p * v0b.x; a0.w = a0.w * cr + p * v0b.y;
        m0 = mn;
    }
    float M = fmaxf(m0, m1);
    float c0 = __expf(m0 - M), c1 = __expf(m1 - M);
    float den = den0 * c0 + den1 * c1;
    float4 acc;
    acc.x = a0.x * c0 + a1.x * c1;
    acc.y = a0.y * c0 + a1.y * c1;
    acc.z = a0.z * c0 + a1.z * c1;
    acc.w = a0.w * c0 + a1.w * c1;

    float inv = 1.f / (den + 1e-16f);
    __shared__ float sm[HH * CC];
    sm[wid * CC + lane * 4 + 0] = acc.x * inv;
    sm[wid * CC + lane * 4 + 1] = acc.y * inv;
    sm[wid * CC + lane * 4 + 2] = acc.z * inv;
    sm[wid * CC + lane * 4 + 3] = acc.w * inv;
    __syncthreads();
    if (threadIdx.x < CC) {
        float s = 0.f;
        #pragma unroll
        for (int h = 0; h < HH; h++) s += sm[h * CC + threadIdx.x];
        attn[(size_t)node * CC + threadIdx.x] = s * 0.125f;
    }
}

// ---------------- beta-gate + (residual) + LayerNorm + ReLU -> bf16 out ----------------
__global__ __launch_bounds__(256)
void gate_ln_kernel(const float* __restrict__ attn, const float* __restrict__ skip,
                    const float* __restrict__ Wb, const float* __restrict__ gam,
                    const float* __restrict__ bet, const __nv_bfloat16* __restrict__ res,
                    __nv_bfloat16* __restrict__ out, int N) {
    int node = blockIdx.x * 8 + (threadIdx.x >> 5);
    if (node >= N) return;
    int lane = threadIdx.x & 31;
    int c = lane * 4;

    float4 a  = *(const float4*)(attn + (size_t)node * CC + c);
    float4 xr = *(const float4*)(skip + (size_t)node * CC + c);
    float4 w0 = *(const float4*)(Wb + c);
    float4 w1 = *(const float4*)(Wb + 128 + c);
    float4 w2 = *(const float4*)(Wb + 256 + c);

    float t = a.x * w0.x + a.y * w0.y + a.z * w0.z + a.w * w0.w
            + xr.x * w1.x + xr.y * w1.y + xr.z * w1.z + xr.w * w1.w
            + (a.x - xr.x) * w2.x + (a.y - xr.y) * w2.y
            + (a.z - xr.z) * w2.z + (a.w - xr.w) * w2.w;
    #pragma unroll
    for (int off = 16; off; off >>= 1) t += __shfl_xor_sync(0xffffffffu, t, off);
    float beta = 1.f / (1.f + __expf(-t));

    float4 y;
    y.x = beta * xr.x + (1.f - beta) * a.x;
    y.y = beta * xr.y + (1.f - beta) * a.y;
    y.z = beta * xr.z + (1.f - beta) * a.z;
    y.w = beta * xr.w + (1.f - beta) * a.w;
    if (res) {
        uint2 rr = *(const uint2*)(res + (size_t)node * CC + c);
        float2 r0 = __bfloat1622float2(*(const __nv_bfloat162*)&rr.x);
        float2 r1 = __bfloat1622float2(*(const __nv_bfloat162*)&rr.y);
        y.x += r0.x; y.y += r0.y; y.z += r1.x; y.w += r1.y;
    }
    float s = y.x + y.y + y.z + y.w;
    #pragma unroll
    for (int off = 16; off; off >>= 1) s += __shfl_xor_sync(0xffffffffu, s, off);
    float mu = s * (1.f / 128.f);
    float dx0 = y.x - mu, dx1 = y.y - mu, dx2 = y.z - mu, dx3 = y.w - mu;
    float q = dx0 * dx0 + dx1 * dx1 + dx2 * dx2 + dx3 * dx3;
    #pragma unroll
    for (int off = 16; off; off >>= 1) q += __shfl_xor_sync(0xffffffffu, q, off);
    float rstd = rsqrtf(q * (1.f / 128.f) + 1e-5f);
    float4 gg = *(const float4*)(gam + c);
    float4 bb = *(const float4*)(bet + c);
    float2 o0, o1;
    o0.x = fmaxf(dx0 * rstd * gg.x + bb.x, 0.f);
    o0.y = fmaxf(dx1 * rstd * gg.y + bb.y, 0.f);
    o1.x = fmaxf(dx2 * rstd * gg.z + bb.z, 0.f);
    o1.y = fmaxf(dx3 * rstd * gg.w + bb.w, 0.f);
    uint2 ow;
    *(__nv_bfloat162*)&ow.x = __float22bfloat162_rn(o0);
    *(__nv_bfloat162*)&ow.y = __float22bfloat162_rn(o1);
    *(uint2*)(out + (size_t)node * CC + c) = ow;
}

// ---------------- pooling: batch is SORTED -> segmented running sums ----------------
__global__ __launch_bounds__(128)
void pool_kernel(const __nv_bfloat16* __restrict__ h, const int* __restrict__ batch,
                 float* __restrict__ psum, float* __restrict__ cnt, int N) {
    int c = threadIdx.x;
    int n0 = blockIdx.x * 64;
    int n1 = min(n0 + 64, N);
    int cur = batch[n0];
    float s = 0.f;
    float k = 0.f;
    for (int n = n0; n < n1; n++) {
        int b = batch[n];
        if (b != cur) {
            atomicAdd(&psum[cur * CC + c], s);
            if (c == 0) atomicAdd(&cnt[cur], k);
            s = 0.f; k = 0.f; cur = b;
        }
        s += __bfloat162float(h[(size_t)n * CC + c]);
        k += 1.f;
    }
    atomicAdd(&psum[cur * CC + c], s);
    if (c == 0) atomicAdd(&cnt[cur], k);
}

// ---------------- classifier ----------------
__global__ void cls_kernel(const float* __restrict__ psum, const float* __restrict__ cnt,
                           const float* __restrict__ Wc1, const float* __restrict__ bc1,
                           const float* __restrict__ Wc2, const float* __restrict__ bc2,
                           float* __restrict__ out) {
    int g = threadIdx.x;
    if (g >= NG) return;
    float invc = 1.f / fmaxf(cnt[g], 1.f);
    float pooled[CC];
    #pragma unroll 8
    for (int c = 0; c < CC; c++) pooled[c] = psum[g * CC + c] * invc;
    float r = bc2[0];
    for (int j = 0; j < 64; j++) {
        float z = bc1[j];
        #pragma unroll 8
        for (int c = 0; c < CC; c++) z += pooled[c] * Wc1[c * 64 + j];
        r += fmaxf(z, 0.f) * Wc2[j];
    }
    out[g] = r;
}

// ---------------- launch ----------------
extern "C" void kernel_launch(void* const* d_in, const int* in_sizes, int n_in,
                              void* d_out, int out_size) {
    const int N = NN, E = EE;
    const int*   x     = (const int*)d_in[0];
    const int*   ei    = (const int*)d_in[1];
    const int*   src   = ei;
    const int*   dst   = ei + E;
    const int*   batch = (const int*)d_in[2];
    const float* emb   = (const float*)d_in[3];

    const float *Wq0 = (const float*)d_in[4],  *bq0 = (const float*)d_in[5];
    const float *Wk0 = (const float*)d_in[6],  *bk0 = (const float*)d_in[7];
    const float *Wv0 = (const float*)d_in[8],  *bv0 = (const float*)d_in[9];
    const float *Ws0 = (const float*)d_in[10], *bs0 = (const float*)d_in[11];
    const float *Wb0 = (const float*)d_in[12];
    const float *g0  = (const float*)d_in[13], *be0 = (const float*)d_in[14];
    const float *Wq1 = (const float*)d_in[15], *bq1 = (const float*)d_in[16];
    const float *Wk1 = (const float*)d_in[17], *bk1 = (const float*)d_in[18];
    const float *Wv1 = (const float*)d_in[19], *bv1 = (const float*)d_in[20];
    const float *Ws1 = (const float*)d_in[21], *bs1 = (const float*)d_in[22];
    const float *Wb1 = (const float*)d_in[23];
    const float *g1  = (const float*)d_in[24], *be1 = (const float*)d_in[25];
    const float *Wc1 = (const float*)d_in[26], *bc1 = (const float*)d_in[27];
    const float *Wc2 = (const float*)d_in[28], *bc2 = (const float*)d_in[29];

    __nv_bfloat16 *hb, *qbb, *kv, *h1, *h2, *Wt;
    float *skip, *attn, *bcat, *pool, *cnt;
    int *deg, *rowptr, *wofs, *col, *bsum, *bsum2;
    cudaGetSymbolAddress((void**)&hb,     g_hb);
    cudaGetSymbolAddress((void**)&qbb,    g_qb);
    cudaGetSymbolAddress((void**)&kv,     g_kv);
    cudaGetSymbolAddress((void**)&skip,   g_skip);
    cudaGetSymbolAddress((void**)&attn,   g_attn);
    cudaGetSymbolAddress((void**)&h1,     g_h1);
    cudaGetSymbolAddress((void**)&h2,     g_h2);
    cudaGetSymbolAddress((void**)&Wt,     g_Wt);
    cudaGetSymbolAddress((void**)&bcat,   g_bcat);
    cudaGetSymbolAddress((void**)&pool,   g_pool);
    cudaGetSymbolAddress((void**)&cnt,    g_cnt);
    cudaGetSymbolAddress((void**)&deg,    g_deg);
    cudaGetSymbolAddress((void**)&rowptr, g_rowptr);
    cudaGetSymbolAddress((void**)&wofs,   g_wofs);
    cudaGetSymbolAddress((void**)&col,    g_col);
    cudaGetSymbolAddress((void**)&bsum,   g_bsum);
    cudaGetSymbolAddress((void**)&bsum2,  g_bsum2);

    const int NB = (N + 255) / 256;

    // CSR build (by dst)
    cudaMemsetAsync(deg, 0, N * sizeof(int));
    hist_kernel<<<(E + 255) / 256, 256>>>(dst, deg, E);
    scan_block_kernel<<<NB, 256>>>(deg, rowptr, bsum, N);
    scan_bsum_kernel<<<1, 256>>>(bsum, bsum2, NB);
    scan_add_kernel<<<NB, 256>>>(rowptr, bsum2, N);
    copyofs_kernel<<<(N + 255) / 256, 256>>>(rowptr, wofs, N);
    scatter_kernel<<<(E + 255) / 256, 256>>>(src, dst, wofs, col, E);

    // embedding
    embed_kernel<<<(N * 32 + 255) / 256, 256>>>(x, emb, hb, N);

    dim3 ggrid(NOUT / GBN, (N + GBM - 1) / GBM);   // (13, 391)

    // ---- layer 0 (K = 256) ----
    pack_kernel<<<(NOUT * 256 + 255) / 256, 256>>>(Wq0, Wk0, Wv0, Ws0, bq0, bk0, bv0, bs0,
                                                   Wt, bcat, 256, 8);
    gemm_bf16_kernel<<<ggrid, 256>>>(hb, Wt, bcat, qbb, kv, skip, N, 256);
    attn_kernel<<<N, 256>>>(qbb, kv, rowptr, col, attn);
    gate_ln_kernel<<<(N + 7) / 8, 256>>>(attn, skip, Wb0, g0, be0,
                                         (const __nv_bfloat16*)nullptr, h1, N);

    // ---- layer 1 (K = 128, residual) ----
    pack_kernel<<<(NOUT * 128 + 255) / 256, 256>>>(Wq1, Wk1, Wv1, Ws1, bq1, bk1, bv1, bs1,
                                                   Wt, bcat, 128, 7);
    gemm_bf16_kernel<<<ggrid, 256>>>(h1, Wt, bcat, qbb, kv, skip, N, 128);
    attn_kernel<<<N, 256>>>(qbb, kv, rowptr, col, attn);
    gate_ln_kernel<<<(N + 7) / 8, 256>>>(attn, skip, Wb1, g1, be1, h1, h2, N);

    // ---- pool + classifier ----
    cudaMemsetAsync(pool, 0, NG * CC * sizeof(float));
    cudaMemsetAsync(cnt, 0, NG * sizeof(float));
    pool_kernel<<<(N + 63) / 64, 128>>>(h2, batch, pool, cnt, N);
    cls_kernel<<<1, 64>>>(pool, cnt, Wc1, bc1, Wc2, bc2, (float*)d_out);
}